// round 14
// baseline (speedup 1.0000x reference)
#include <cuda_runtime.h>
#include <math.h>
#include <stdint.h>

#define SEQ 2048
#define HID 2048
#define NH 32
#define NKV 8
#define HD 64
#define KVW (NKV*HD)       /* 512 */
#define QKVW (HID + 2*KVW) /* 3072 */

// ---------------- scratch ------------------------------------------------------
__device__ float g_qkv[SEQ * QKVW];
__device__ float g_att[SEQ * HID];
__device__ float g_hs32[SEQ * HID];
__device__ float g_wqkvT[QKVW * HID];
__device__ float g_woT[HID * HID];

// ================= helpers =================
__device__ __forceinline__ uint32_t smem_u32(const void* p) {
    uint32_t a;
    asm("{ .reg .u64 t; cvta.to.shared.u64 t, %1; cvt.u32.u64 %0, t; }" : "=r"(a) : "l"(p));
    return a;
}
__device__ __forceinline__ uint32_t f2tf32(float f) {
    uint32_t r;
    asm("cvt.rna.tf32.f32 %0, %1;" : "=r"(r) : "f"(f));
    return r;
}
__device__ __forceinline__ float f2tf32f(float f) {
    return __uint_as_float(f2tf32(f));
}
__device__ __forceinline__ float ex2(float x) {
    float r;
    asm("ex2.approx.ftz.f32 %0, %1;" : "=f"(r) : "f"(x));
    return r;
}
// pair-permutation of the contraction dim within each 8-group:
// (0,4),(1,5),(2,6),(3,7) -> (0,1),(2,3),(4,5),(6,7)
__device__ __forceinline__ int perm8(int c) {
    const int l = c & 7;
    return (c & ~7) | ((l & 3) << 1) | (l >> 2);
}
#define CP_ASYNC16(dst, src) \
    asm volatile("cp.async.cg.shared.global [%0], [%1], 16;" :: "r"(dst), "l"(src))
#define CP_COMMIT() asm volatile("cp.async.commit_group;" ::: "memory")
#define CP_WAIT(n)  asm volatile("cp.async.wait_group %0;" :: "n"(n) : "memory")

__device__ __forceinline__ void mma_tf32_16x8x8(float& c0, float& c1, float& c2, float& c3,
                                                uint32_t a0, uint32_t a1, uint32_t a2, uint32_t a3,
                                                uint32_t b0, uint32_t b1) {
    asm volatile(
        "mma.sync.aligned.m16n8k8.row.col.f32.tf32.tf32.f32 "
        "{%0,%1,%2,%3}, {%4,%5,%6,%7}, {%8,%9}, {%0,%1,%2,%3};"
        : "+f"(c0), "+f"(c1), "+f"(c2), "+f"(c3)
        : "r"(a0), "r"(a1), "r"(a2), "r"(a3), "r"(b0), "r"(b1));
}

// ---------------- prep 0: hs round-copy with K-dim pair-permutation -----------
__global__ __launch_bounds__(256)
void prep_copy(const float* __restrict__ hs, float* __restrict__ hs32)
{
    const int i = (blockIdx.x * 256 + threadIdx.x) * 4;   // cols i..i+3 same 8-group half
    float4 v = *(const float4*)(hs + i);
    hs32[(i & ~7) | ((((i + 0) & 3) << 1) | (((i + 0) & 7) >> 2))] = f2tf32f(v.x);
    hs32[(i & ~7) | ((((i + 1) & 3) << 1) | (((i + 1) & 7) >> 2))] = f2tf32f(v.y);
    hs32[(i & ~7) | ((((i + 2) & 3) << 1) | (((i + 2) & 7) >> 2))] = f2tf32f(v.z);
    hs32[(i & ~7) | ((((i + 3) & 3) << 1) | (((i + 3) & 7) >> 2))] = f2tf32f(v.w);
}

// ---------------- prep 1: wq/wk/wv transpose + round + K-perm -----------------
__global__ __launch_bounds__(256)
void prep_wqkv(const float* __restrict__ wq, const float* __restrict__ wk,
               const float* __restrict__ wv, float* __restrict__ wqkvT)
{
    __shared__ float t[32][33];
    const int bx = blockIdx.x;
    const int tx = threadIdx.x & 31;
    const int ty = threadIdx.x >> 5;
    const float* in;
    float* out;
    int N, lb;
    if (bx < 4096)       { in = wq; out = wqkvT;                          N = HID; lb = bx; }
    else if (bx < 5120)  { in = wk; out = wqkvT + (size_t)HID * HID;      N = KVW; lb = bx - 4096; }
    else                 { in = wv; out = wqkvT + (size_t)(HID+KVW)*HID;  N = KVW; lb = bx - 5120; }
    const int gw = N / 32;
    const int bxx = (lb % gw) * 32;
    const int byy = (lb / gw) * 32;
#pragma unroll
    for (int i = 0; i < 32; i += 8)
        t[ty + i][tx] = in[(size_t)(byy + ty + i) * N + bxx + tx];
    __syncthreads();
    const int pc = byy + perm8(tx);        // permuted K index
#pragma unroll
    for (int i = 0; i < 32; i += 8)
        out[(size_t)(bxx + ty + i) * HID + pc] = f2tf32f(t[tx][ty + i]);
}

// ---------------- prep 2: wo transpose + round + K-perm -----------------------
__global__ __launch_bounds__(256)
void prep_wo(const float* __restrict__ wo, float* __restrict__ woT)
{
    __shared__ float t[32][33];
    const int bxx = ((int)blockIdx.x % 64) * 32;
    const int byy = ((int)blockIdx.x / 64) * 32;
    const int tx = threadIdx.x & 31;
    const int ty = threadIdx.x >> 5;
#pragma unroll
    for (int i = 0; i < 32; i += 8)
        t[ty + i][tx] = wo[(size_t)(byy + ty + i) * HID + bxx + tx];
    __syncthreads();
    const int pc = byy + perm8(tx);
#pragma unroll
    for (int i = 0; i < 32; i += 8)
        woT[(size_t)(bxx + ty + i) * HID + pc] = f2tf32f(t[tx][ty + i]);
}

// ---------------- tf32 mma.sync GEMM (K-dim pre-permuted; LDS.64 frags) -------
#define GPAD 40
#define GBUF (128 * GPAD)
#define G_SMEM_BYTES (4 * GBUF * 4)   /* 81920 B */

__global__ __launch_bounds__(256)
void gemm_mma(const float* __restrict__ A, const float* __restrict__ BT,
              float* __restrict__ C, int M, int N, int K, int roundOut)
{
    extern __shared__ float sm[];
    float* sA = sm;
    float* sB = sm + 2 * GBUF;

    const int tid  = threadIdx.x;
    const int wid  = tid >> 5;
    const int lane = tid & 31;
    const int g    = lane >> 2;
    const int tg   = lane & 3;
    const int wm   = (wid & 3) * 32;
    const int wn   = (wid >> 2) * 64;
    const int m0 = blockIdx.y * 128;
    const int n0 = blockIdx.x * 128;

    const int lrow  = tid >> 1;
    const int lcol  = (tid & 1) * 16;
    const float* gA = A  + (size_t)(m0 + lrow) * K + lcol;
    const float* gB = BT + (size_t)(n0 + lrow) * K + lcol;
    const uint32_t sbase = smem_u32(sm);
    const uint32_t sArow = sbase + (uint32_t)(lrow * GPAD + lcol) * 4u;
    const uint32_t sBrow = sArow + 2u * GBUF * 4u;

    float acc[2][8][4];
#pragma unroll
    for (int mt = 0; mt < 2; mt++)
#pragma unroll
        for (int nt = 0; nt < 8; nt++)
#pragma unroll
            for (int i = 0; i < 4; i++) acc[mt][nt][i] = 0.f;

    const int nch = K >> 5;
    {
#pragma unroll
        for (int j = 0; j < 4; j++) {
            CP_ASYNC16(sArow + j * 16u, gA + j * 4);
            CP_ASYNC16(sBrow + j * 16u, gB + j * 4);
        }
        CP_COMMIT();
    }

    for (int c = 0; c < nch; ++c) {
        const int buf = c & 1;
        if (c + 1 < nch) {
            const uint32_t off = (uint32_t)(((c + 1) & 1) * GBUF) * 4u;
            const float* pa = gA + (c + 1) * 32;
            const float* pb = gB + (c + 1) * 32;
#pragma unroll
            for (int j = 0; j < 4; j++) {
                CP_ASYNC16(sArow + off + j * 16u, pa + j * 4);
                CP_ASYNC16(sBrow + off + j * 16u, pb + j * 4);
            }
            CP_COMMIT();
            CP_WAIT(1);
        } else {
            CP_WAIT(0);
        }
        __syncthreads();

        const float* tA = sA + buf * GBUF;
        const float* tB = sB + buf * GBUF;

#pragma unroll
        for (int ks = 0; ks < 4; ++ks) {
            const int kk2 = ks * 8 + 2 * tg;   // permuted pair position
            uint32_t af[2][4];
#pragma unroll
            for (int mt = 0; mt < 2; mt++) {
                const int r = wm + mt * 16 + g;
                const float2 aA = *(const float2*)(tA + r * GPAD + kk2);
                const float2 aB = *(const float2*)(tA + (r + 8) * GPAD + kk2);
                af[mt][0] = __float_as_uint(aA.x);
                af[mt][2] = __float_as_uint(aA.y);
                af[mt][1] = __float_as_uint(aB.x);
                af[mt][3] = __float_as_uint(aB.y);
            }
            uint32_t bf[8][2];
#pragma unroll
            for (int nt = 0; nt < 8; nt++) {
                const int r = wn + nt * 8 + g;
                const float2 bb = *(const float2*)(tB + r * GPAD + kk2);
                bf[nt][0] = __float_as_uint(bb.x);
                bf[nt][1] = __float_as_uint(bb.y);
            }
#pragma unroll
            for (int mt = 0; mt < 2; mt++)
#pragma unroll
                for (int nt = 0; nt < 8; nt++)
                    mma_tf32_16x8x8(acc[mt][nt][0], acc[mt][nt][1],
                                    acc[mt][nt][2], acc[mt][nt][3],
                                    af[mt][0], af[mt][1], af[mt][2], af[mt][3],
                                    bf[nt][0], bf[nt][1]);
        }
        __syncthreads();
    }

#pragma unroll
    for (int mt = 0; mt < 2; mt++) {
        const int r0 = m0 + wm + mt * 16 + g;
#pragma unroll
        for (int nt = 0; nt < 8; nt++) {
            const int col = n0 + wn + nt * 8 + 2 * tg;
            float2 v0 = make_float2(acc[mt][nt][0], acc[mt][nt][1]);
            float2 v1 = make_float2(acc[mt][nt][2], acc[mt][nt][3]);
            if (roundOut) {
                v0.x = f2tf32f(v0.x); v0.y = f2tf32f(v0.y);
                v1.x = f2tf32f(v1.x); v1.y = f2tf32f(v1.y);
            }
            *(float2*)(C + (size_t)r0 * N + col) = v0;
            *(float2*)(C + (size_t)(r0 + 8) * N + col) = v1;
        }
    }
}

// ---------------- fused RMSNorm + RoPE (q + k; stores d-permuted) -------------
__global__ __launch_bounds__(256)
void norm_rope_all(float* __restrict__ qkv, const float* __restrict__ qw,
                   const float* __restrict__ kw, const int* __restrict__ pos)
{
    const int bx = blockIdx.x;
    float* x; const float* w; int nheads; float scale; int lb;
    if (bx < 8192) { x = qkv;       w = qw; nheads = NH;  scale = 0.125f; lb = bx; }
    else           { x = qkv + HID; w = kw; nheads = NKV; scale = 1.0f;   lb = bx - 8192; }

    const int gw = (lb * 256 + (int)threadIdx.x) >> 5;
    const int lane = threadIdx.x & 31;
    const int s = gw / nheads;
    const int hh = gw - s * nheads;

    float* p = x + (size_t)s * QKVW + hh * HD;
    float x0 = p[lane];
    float x1 = p[lane + 32];

    float ss = x0 * x0 + x1 * x1;
#pragma unroll
    for (int o = 16; o; o >>= 1) ss += __shfl_xor_sync(0xffffffffu, ss, o);
    const float inv = rsqrtf(ss * (1.f / 64.f) + 1e-6f);
    x0 *= inv * w[lane];
    x1 *= inv * w[lane + 32];

    const float ang = (float)pos[s] * __expf(-(float)lane * (1.f / 32.f) * 9.2103403719761836f);
    float sn, c;
    sincosf(ang, &sn, &c);
    const float r0 = f2tf32f((x0 * c - x1 * sn) * scale);
    const float r1 = f2tf32f((x1 * c + x0 * sn) * scale);
    __syncwarp();                           // all lanes done reading before permuted stores
    p[perm8(lane)]      = r0;
    p[perm8(lane + 32)] = r1;
}

// ---------------- causal flash attention --------------------------------------
// Q/K head-dim pre-permuted in gmem -> QK fragment pairs are adjacent:
// one conflict-free LDS.64 per B-frag (KPAD=72: bank 8g+2tg). V natural (VPAD=72).
#define KPAD 72
#define VPAD 72
#define KTILE (64 * KPAD)
#define VTILE (64 * VPAD)
#define AT_SMEM_FLOATS (2 * KTILE + 2 * VTILE)
#define AT_SMEM_BYTES  (AT_SMEM_FLOATS * 4)    /* 73728 B */
#define L2E 1.4426950408889634f

__global__ __launch_bounds__(256, 2)
void attn_mma(const float* __restrict__ qb, const float* __restrict__ kb,
              const float* __restrict__ vb, float* __restrict__ ob)
{
    extern __shared__ float sm[];
    // layout: [Ks0, Ks1, Vs0, Vs1]

    const int tid = threadIdx.x;
    const int wid = tid >> 5;
    const int lane = tid & 31;
    const int g = lane >> 2;
    const int tg = lane & 3;
    const int nqt = SEQ / 128;
    const int qt = nqt - 1 - ((int)blockIdx.x >> 5);
    const int h = (int)blockIdx.x & 31;
    const int kvh = h >> 2;
    const int dlim = 2 * wid + 2;

    const int lr = tid >> 2;
    const int lc4 = (tid & 3) * 16;
    const uint32_t sbase = smem_u32(sm);
    const uint32_t sKrow = sbase + (uint32_t)(lr * KPAD + lc4) * 4u;
    const uint32_t sVrow = sbase + (uint32_t)(2 * KTILE + lr * VPAD + lc4) * 4u;
    const float* kbase = kb + (size_t)kvh * HD + lc4;
    const float* vbase = vb + (size_t)kvh * HD + lc4;

    // ---- Q fragments: float2 loads (d-dim pre-permuted, pre-scaled) ----
    uint32_t aq[8][4];
    {
        const float* qp = qb + (size_t)(qt * 128 + wid * 16) * QKVW + h * HD;
#pragma unroll
        for (int ks = 0; ks < 8; ks++) {
            const int kk2 = ks * 8 + 2 * tg;
            const float2 qa = *(const float2*)(qp + (size_t)g * QKVW + kk2);
            const float2 qc = *(const float2*)(qp + (size_t)(g + 8) * QKVW + kk2);
            aq[ks][0] = __float_as_uint(qa.x);
            aq[ks][2] = __float_as_uint(qa.y);
            aq[ks][1] = __float_as_uint(qc.x);
            aq[ks][3] = __float_as_uint(qc.y);
        }
    }

    float o[8][4];
#pragma unroll
    for (int nt = 0; nt < 8; nt++)
#pragma unroll
        for (int i = 0; i < 4; i++) o[nt][i] = 0.f;
    float m0 = -1e30f, m1 = -1e30f, l0 = 0.f, l1 = 0.f;

    const int r0g = qt * 128 + wid * 16 + g;
    const int r1g = r0g + 8;
    const int nkt = 2 * qt + 2;

    // ---- prefetch tile 0 ----
    {
        const float* kp = kbase + (size_t)lr * QKVW;
        const float* vp = vbase + (size_t)lr * QKVW;
#pragma unroll
        for (int j = 0; j < 4; j++) {
            CP_ASYNC16(sKrow + j * 16u, kp + j * 4);
            CP_ASYNC16(sVrow + j * 16u, vp + j * 4);
        }
        CP_COMMIT();
    }

    for (int kt = 0; kt < nkt; ++kt) {
        if (kt + 1 < nkt) {
            const uint32_t kb_off = (uint32_t)(((kt + 1) & 1) * KTILE) * 4u;
            const uint32_t vb_off = (uint32_t)(((kt + 1) & 1) * VTILE) * 4u;
            const float* kp = kbase + (size_t)((kt + 1) * 64 + lr) * QKVW;
            const float* vp = vbase + (size_t)((kt + 1) * 64 + lr) * QKVW;
#pragma unroll
            for (int j = 0; j < 4; j++) {
                CP_ASYNC16(sKrow + kb_off + j * 16u, kp + j * 4);
                CP_ASYNC16(sVrow + vb_off + j * 16u, vp + j * 4);
            }
            CP_COMMIT();
            CP_WAIT(1);
        } else {
            CP_WAIT(0);
        }
        __syncthreads();

        const float* Ks = sm + (kt & 1) * KTILE;
        const float* Vs = sm + 2 * KTILE + (kt & 1) * VTILE;

        const bool diag = (kt == 2 * qt);
        const bool active = !(kt == 2 * qt + 1 && wid < 4);
        if (active) {
            // ---- S = Q @ K^T (one LDS.64 per B-frag) ----
            float s[8][4];
#pragma unroll
            for (int nt = 0; nt < 8; nt++)
#pragma unroll
                for (int i = 0; i < 4; i++) s[nt][i] = 0.f;

#pragma unroll
            for (int ks = 0; ks < 8; ks++) {
                const int kk2 = ks * 8 + 2 * tg;
#pragma unroll
                for (int nt = 0; nt < 8; nt++) {
                    if (diag && nt >= dlim) continue;
                    const float2 kb2 = *(const float2*)(Ks + (nt * 8 + g) * KPAD + kk2);
                    mma_tf32_16x8x8(s[nt][0], s[nt][1], s[nt][2], s[nt][3],
                                    aq[ks][0], aq[ks][1], aq[ks][2], aq[ks][3],
                                    __float_as_uint(kb2.x), __float_as_uint(kb2.y));
                }
            }

            // ---- causal mask ----
            if (kt >= 2 * qt) {
#pragma unroll
                for (int nt = 0; nt < 8; nt++) {
                    const int j0 = kt * 64 + nt * 8 + 2 * tg;
                    if (j0 > r0g)     s[nt][0] = -1e30f;
                    if (j0 + 1 > r0g) s[nt][1] = -1e30f;
                    if (j0 > r1g)     s[nt][2] = -1e30f;
                    if (j0 + 1 > r1g) s[nt][3] = -1e30f;
                }
            }

            // ---- online softmax ----
            float mx0 = -1e30f, mx1 = -1e30f;
#pragma unroll
            for (int nt = 0; nt < 8; nt++) {
                mx0 = fmaxf(mx0, fmaxf(s[nt][0], s[nt][1]));
                mx1 = fmaxf(mx1, fmaxf(s[nt][2], s[nt][3]));
            }
            mx0 = fmaxf(mx0, __shfl_xor_sync(0xffffffffu, mx0, 1));
            mx0 = fmaxf(mx0, __shfl_xor_sync(0xffffffffu, mx0, 2));
            mx1 = fmaxf(mx1, __shfl_xor_sync(0xffffffffu, mx1, 1));
            mx1 = fmaxf(mx1, __shfl_xor_sync(0xffffffffu, mx1, 2));

            const float mn0 = fmaxf(m0, mx0);
            const float mn1 = fmaxf(m1, mx1);
            const float al0 = ex2((m0 - mn0) * L2E);
            const float al1 = ex2((m1 - mn1) * L2E);
            float sum0 = 0.f, sum1 = 0.f;
#pragma unroll
            for (int nt = 0; nt < 8; nt++) {
                s[nt][0] = ex2((s[nt][0] - mn0) * L2E);
                s[nt][1] = ex2((s[nt][1] - mn0) * L2E);
                s[nt][2] = ex2((s[nt][2] - mn1) * L2E);
                s[nt][3] = ex2((s[nt][3] - mn1) * L2E);
                sum0 += s[nt][0] + s[nt][1];
                sum1 += s[nt][2] + s[nt][3];
            }
            sum0 += __shfl_xor_sync(0xffffffffu, sum0, 1);
            sum0 += __shfl_xor_sync(0xffffffffu, sum0, 2);
            sum1 += __shfl_xor_sync(0xffffffffu, sum1, 1);
            sum1 += __shfl_xor_sync(0xffffffffu, sum1, 2);
            m0 = mn0; m1 = mn1;
            l0 = l0 * al0 + sum0;
            l1 = l1 * al1 + sum1;
#pragma unroll
            for (int nt = 0; nt < 8; nt++) {
                o[nt][0] *= al0; o[nt][1] *= al0;
                o[nt][2] *= al1; o[nt][3] *= al1;
            }

            // ---- O += P @ V ----
            const int qbase = lane & ~3;
            const int s1 = qbase + (tg >> 1);
            const int s2 = s1 + 2;
            const bool odd = (tg & 1);
#pragma unroll
            for (int ks = 0; ks < 8; ks++) {
                if (diag && ks >= dlim) continue;
                const float v0 = __shfl_sync(0xffffffffu, s[ks][0], s1);
                const float v1 = __shfl_sync(0xffffffffu, s[ks][1], s1);
                const float v2 = __shfl_sync(0xffffffffu, s[ks][2], s1);
                const float v3 = __shfl_sync(0xffffffffu, s[ks][3], s1);
                const float w0 = __shfl_sync(0xffffffffu, s[ks][0], s2);
                const float w1 = __shfl_sync(0xffffffffu, s[ks][1], s2);
                const float w2 = __shfl_sync(0xffffffffu, s[ks][2], s2);
                const float w3 = __shfl_sync(0xffffffffu, s[ks][3], s2);
                const uint32_t a0 = f2tf32(odd ? v1 : v0);
                const uint32_t a1 = f2tf32(odd ? v3 : v2);
                const uint32_t a2 = f2tf32(odd ? w1 : w0);
                const uint32_t a3 = f2tf32(odd ? w3 : w2);
                const int kk = ks * 8 + tg;
#pragma unroll
                for (int nt = 0; nt < 8; nt++) {
                    const uint32_t b0 = __float_as_uint(Vs[kk * VPAD + nt * 8 + g]);
                    const uint32_t b1 = __float_as_uint(Vs[(kk + 4) * VPAD + nt * 8 + g]);
                    mma_tf32_16x8x8(o[nt][0], o[nt][1], o[nt][2], o[nt][3],
                                    a0, a1, a2, a3, b0, b1);
                }
            }
        }
        __syncthreads();
    }

    // ---- epilogue: tf32-round, store K-PERMUTED (feeds O-proj A operand) ----
    const float il0 = 1.f / l0;
    const float il1 = 1.f / l1;
#pragma unroll
    for (int nt = 0; nt < 8; nt++) {
        const int c0 = h * HD + nt * 8 + 2 * tg;
        const int c1 = c0 + 1;
        ob[(size_t)r0g * HID + perm8(c0)] = f2tf32f(o[nt][0] * il0);
        ob[(size_t)r0g * HID + perm8(c1)] = f2tf32f(o[nt][1] * il0);
        ob[(size_t)r1g * HID + perm8(c0)] = f2tf32f(o[nt][2] * il1);
        ob[(size_t)r1g * HID + perm8(c1)] = f2tf32f(o[nt][3] * il1);
    }
}

// ---------------- launch ------------------------------------------------------
extern "C" void kernel_launch(void* const* d_in, const int* in_sizes, int n_in,
                              void* d_out, int out_size)
{
    const float* hs  = (const float*)d_in[0];
    const int*   pos = (const int*)  d_in[1];
    const float* wq  = (const float*)d_in[2];
    const float* wk  = (const float*)d_in[3];
    const float* wv  = (const float*)d_in[4];
    const float* wo  = (const float*)d_in[5];
    const float* qw  = (const float*)d_in[6];
    const float* kw  = (const float*)d_in[7];
    float* out = (float*)d_out;

    float *pqkv, *pa, *phs, *pwqkvT, *pwoT;
    cudaGetSymbolAddress((void**)&pqkv, g_qkv);
    cudaGetSymbolAddress((void**)&pa, g_att);
    cudaGetSymbolAddress((void**)&phs, g_hs32);
    cudaGetSymbolAddress((void**)&pwqkvT, g_wqkvT);
    cudaGetSymbolAddress((void**)&pwoT, g_woT);

    cudaFuncSetAttribute(gemm_mma, cudaFuncAttributeMaxDynamicSharedMemorySize,
                         G_SMEM_BYTES);
    cudaFuncSetAttribute(attn_mma, cudaFuncAttributeMaxDynamicSharedMemorySize,
                         AT_SMEM_BYTES);

    prep_copy<<<4096, 256>>>(hs, phs);                       // launch 0
    prep_wqkv<<<6144, 256>>>(wq, wk, wv, pwqkvT);            // launch 1
    prep_wo<<<4096, 256>>>(wo, pwoT);                        // launch 2

    // launch 3 (ncu-captured): fused QKV projection
    gemm_mma<<<dim3(QKVW / 128, SEQ / 128), 256, G_SMEM_BYTES>>>(phs, pwqkvT, pqkv, SEQ, QKVW, HID, 1);

    norm_rope_all<<<10240, 256>>>(pqkv, qw, kw, pos);        // launch 4

    float* pk = pqkv + HID;
    float* pv = pqkv + HID + KVW;
    attn_mma<<<512, 256, AT_SMEM_BYTES>>>(pqkv, pk, pv, pa); // launch 5

    gemm_mma<<<dim3(HID / 128, SEQ / 128), 256, G_SMEM_BYTES>>>(pa, pwoT, out, SEQ, HID, HID, 0);
}

// round 15
// speedup vs baseline: 1.0543x; 1.0543x over previous
#include <cuda_runtime.h>
#include <math.h>
#include <stdint.h>

#define SEQ 2048
#define HID 2048
#define NH 32
#define NKV 8
#define HD 64
#define KVW (NKV*HD)       /* 512 */
#define QKVW (HID + 2*KVW) /* 3072 */

// ---------------- scratch ------------------------------------------------------
__device__ float g_qkv[SEQ * QKVW];
__device__ float g_att[SEQ * HID];
__device__ float g_hs32[SEQ * HID];
__device__ float g_wqkvT[QKVW * HID];
__device__ float g_woT[HID * HID];

// ================= helpers =================
__device__ __forceinline__ uint32_t smem_u32(const void* p) {
    uint32_t a;
    asm("{ .reg .u64 t; cvta.to.shared.u64 t, %1; cvt.u32.u64 %0, t; }" : "=r"(a) : "l"(p));
    return a;
}
__device__ __forceinline__ uint32_t f2tf32(float f) {
    uint32_t r;
    asm("cvt.rna.tf32.f32 %0, %1;" : "=r"(r) : "f"(f));
    return r;
}
__device__ __forceinline__ float f2tf32f(float f) {
    return __uint_as_float(f2tf32(f));
}
__device__ __forceinline__ float ex2(float x) {
    float r;
    asm("ex2.approx.ftz.f32 %0, %1;" : "=f"(r) : "f"(x));
    return r;
}
#define CP_ASYNC16(dst, src) \
    asm volatile("cp.async.cg.shared.global [%0], [%1], 16;" :: "r"(dst), "l"(src))
#define CP_COMMIT() asm volatile("cp.async.commit_group;" ::: "memory")
#define CP_WAIT(n)  asm volatile("cp.async.wait_group %0;" :: "n"(n) : "memory")

__device__ __forceinline__ void mma_tf32_16x8x8(float& c0, float& c1, float& c2, float& c3,
                                                uint32_t a0, uint32_t a1, uint32_t a2, uint32_t a3,
                                                uint32_t b0, uint32_t b1) {
    asm volatile(
        "mma.sync.aligned.m16n8k8.row.col.f32.tf32.tf32.f32 "
        "{%0,%1,%2,%3}, {%4,%5,%6,%7}, {%8,%9}, {%0,%1,%2,%3};"
        : "+f"(c0), "+f"(c1), "+f"(c2), "+f"(c3)
        : "r"(a0), "r"(a1), "r"(a2), "r"(a3), "r"(b0), "r"(b1));
}

// ---------------- prep 0: hs tf32-round copy ----------------------------------
__global__ __launch_bounds__(256)
void prep_copy(const float* __restrict__ hs, float* __restrict__ hs32)
{
    const int i = (blockIdx.x * 256 + threadIdx.x) * 4;
    float4 v = *(const float4*)(hs + i);
    v.x = f2tf32f(v.x); v.y = f2tf32f(v.y);
    v.z = f2tf32f(v.z); v.w = f2tf32f(v.w);
    *(float4*)(hs32 + i) = v;
}

// ---------------- prep 1: wq/wk/wv transpose + tf32 round ---------------------
__global__ __launch_bounds__(256)
void prep_wqkv(const float* __restrict__ wq, const float* __restrict__ wk,
               const float* __restrict__ wv, float* __restrict__ wqkvT)
{
    __shared__ float t[32][33];
    const int bx = blockIdx.x;
    const int tx = threadIdx.x & 31;
    const int ty = threadIdx.x >> 5;
    const float* in;
    float* out;
    int N, lb;
    if (bx < 4096)       { in = wq; out = wqkvT;                          N = HID; lb = bx; }
    else if (bx < 5120)  { in = wk; out = wqkvT + (size_t)HID * HID;      N = KVW; lb = bx - 4096; }
    else                 { in = wv; out = wqkvT + (size_t)(HID+KVW)*HID;  N = KVW; lb = bx - 5120; }
    const int gw = N / 32;
    const int bxx = (lb % gw) * 32;
    const int byy = (lb / gw) * 32;
#pragma unroll
    for (int i = 0; i < 32; i += 8)
        t[ty + i][tx] = in[(size_t)(byy + ty + i) * N + bxx + tx];
    __syncthreads();
#pragma unroll
    for (int i = 0; i < 32; i += 8)
        out[(size_t)(bxx + ty + i) * HID + byy + tx] = f2tf32f(t[tx][ty + i]);
}

// ---------------- prep 2: wo transpose + tf32 round ---------------------------
__global__ __launch_bounds__(256)
void prep_wo(const float* __restrict__ wo, float* __restrict__ woT)
{
    __shared__ float t[32][33];
    const int bxx = ((int)blockIdx.x % 64) * 32;
    const int byy = ((int)blockIdx.x / 64) * 32;
    const int tx = threadIdx.x & 31;
    const int ty = threadIdx.x >> 5;
#pragma unroll
    for (int i = 0; i < 32; i += 8)
        t[ty + i][tx] = wo[(size_t)(byy + ty + i) * HID + bxx + tx];
    __syncthreads();
#pragma unroll
    for (int i = 0; i < 32; i += 8)
        woT[(size_t)(bxx + ty + i) * HID + byy + tx] = f2tf32f(t[tx][ty + i]);
}

// ---------------- tf32 mma.sync GEMM: 3-stage pipeline, 1 barrier/chunk -------
#define GPAD 36
#define GBUF (128 * GPAD)
#define G_SMEM_BYTES (6 * GBUF * 4)   /* 3 stages x (A+B) = 110592 B */

__global__ __launch_bounds__(256)
void gemm_mma(const float* __restrict__ A, const float* __restrict__ BT,
              float* __restrict__ C, int M, int N, int K, int roundOut)
{
    extern __shared__ float sm[];
    float* sA = sm;                // [3][128][36]
    float* sB = sm + 3 * GBUF;     // [3][128][36]

    const int tid  = threadIdx.x;
    const int wid  = tid >> 5;
    const int lane = tid & 31;
    const int g    = lane >> 2;
    const int tg   = lane & 3;
    const int wm   = (wid & 3) * 32;
    const int wn   = (wid >> 2) * 64;
    const int m0 = blockIdx.y * 128;
    const int n0 = blockIdx.x * 128;

    const int lrow  = tid >> 1;
    const int lcol  = (tid & 1) * 16;
    const float* gA = A  + (size_t)(m0 + lrow) * K + lcol;
    const float* gB = BT + (size_t)(n0 + lrow) * K + lcol;
    const uint32_t sbase = smem_u32(sm);
    const uint32_t sArow = sbase + (uint32_t)(lrow * GPAD + lcol) * 4u;
    const uint32_t sBrow = sArow + 3u * GBUF * 4u;

    float acc[2][8][4];
#pragma unroll
    for (int mt = 0; mt < 2; mt++)
#pragma unroll
        for (int nt = 0; nt < 8; nt++)
#pragma unroll
            for (int i = 0; i < 4; i++) acc[mt][nt][i] = 0.f;

    const int nch = K >> 5;   // 64

    // prologue: prefetch chunks 0 and 1 into stages 0 and 1
#pragma unroll
    for (int p = 0; p < 2; ++p) {
        const uint32_t soff = (uint32_t)(p * GBUF) * 4u;
        const float* pa = gA + p * 32;
        const float* pb = gB + p * 32;
#pragma unroll
        for (int j = 0; j < 4; j++) {
            CP_ASYNC16(sArow + soff + j * 16u, pa + j * 4);
            CP_ASYNC16(sBrow + soff + j * 16u, pb + j * 4);
        }
        CP_COMMIT();
    }

    for (int c = 0; c < nch; ++c) {
        // complete group for chunk c (one younger group may stay in flight)
        if (c + 1 < nch) CP_WAIT(1); else CP_WAIT(0);
        // publish chunk c to all warps; also guarantees every warp finished
        // computing chunk c-1, so stage (c+2)%3 (read at c-1) is reusable.
        __syncthreads();

        if (c + 2 < nch) {
            const int st = (c + 2) % 3;
            const uint32_t soff = (uint32_t)(st * GBUF) * 4u;
            const float* pa = gA + (c + 2) * 32;
            const float* pb = gB + (c + 2) * 32;
#pragma unroll
            for (int j = 0; j < 4; j++) {
                CP_ASYNC16(sArow + soff + j * 16u, pa + j * 4);
                CP_ASYNC16(sBrow + soff + j * 16u, pb + j * 4);
            }
            CP_COMMIT();
        }

        const float* tA = sA + (c % 3) * GBUF;
        const float* tB = sB + (c % 3) * GBUF;

#pragma unroll
        for (int ks = 0; ks < 4; ++ks) {
            const int kk = ks * 8 + tg;
            uint32_t af[2][4];
#pragma unroll
            for (int mt = 0; mt < 2; mt++) {
                const int r = wm + mt * 16 + g;
                af[mt][0] = __float_as_uint(tA[r * GPAD + kk]);
                af[mt][1] = __float_as_uint(tA[(r + 8) * GPAD + kk]);
                af[mt][2] = __float_as_uint(tA[r * GPAD + kk + 4]);
                af[mt][3] = __float_as_uint(tA[(r + 8) * GPAD + kk + 4]);
            }
            uint32_t bf[8][2];
#pragma unroll
            for (int nt = 0; nt < 8; nt++) {
                const int r = wn + nt * 8 + g;
                bf[nt][0] = __float_as_uint(tB[r * GPAD + kk]);
                bf[nt][1] = __float_as_uint(tB[r * GPAD + kk + 4]);
            }
#pragma unroll
            for (int mt = 0; mt < 2; mt++)
#pragma unroll
                for (int nt = 0; nt < 8; nt++)
                    mma_tf32_16x8x8(acc[mt][nt][0], acc[mt][nt][1],
                                    acc[mt][nt][2], acc[mt][nt][3],
                                    af[mt][0], af[mt][1], af[mt][2], af[mt][3],
                                    bf[nt][0], bf[nt][1]);
        }
    }

#pragma unroll
    for (int mt = 0; mt < 2; mt++) {
        const int r0 = m0 + wm + mt * 16 + g;
#pragma unroll
        for (int nt = 0; nt < 8; nt++) {
            const int col = n0 + wn + nt * 8 + 2 * tg;
            float2 v0 = make_float2(acc[mt][nt][0], acc[mt][nt][1]);
            float2 v1 = make_float2(acc[mt][nt][2], acc[mt][nt][3]);
            if (roundOut) {
                v0.x = f2tf32f(v0.x); v0.y = f2tf32f(v0.y);
                v1.x = f2tf32f(v1.x); v1.y = f2tf32f(v1.y);
            }
            *(float2*)(C + (size_t)r0 * N + col) = v0;
            *(float2*)(C + (size_t)(r0 + 8) * N + col) = v1;
        }
    }
}

// ---------------- fused RMSNorm + RoPE (q + k in one launch) ------------------
__global__ __launch_bounds__(256)
void norm_rope_all(float* __restrict__ qkv, const float* __restrict__ qw,
                   const float* __restrict__ kw, const int* __restrict__ pos)
{
    const int bx = blockIdx.x;
    float* x; const float* w; int nheads; float scale; int lb;
    if (bx < 8192) { x = qkv;       w = qw; nheads = NH;  scale = 0.125f; lb = bx; }
    else           { x = qkv + HID; w = kw; nheads = NKV; scale = 1.0f;   lb = bx - 8192; }

    const int gw = (lb * 256 + (int)threadIdx.x) >> 5;
    const int lane = threadIdx.x & 31;
    const int s = gw / nheads;
    const int hh = gw - s * nheads;

    float* p = x + (size_t)s * QKVW + hh * HD;
    float x0 = p[lane];
    float x1 = p[lane + 32];

    float ss = x0 * x0 + x1 * x1;
#pragma unroll
    for (int o = 16; o; o >>= 1) ss += __shfl_xor_sync(0xffffffffu, ss, o);
    const float inv = rsqrtf(ss * (1.f / 64.f) + 1e-6f);
    x0 *= inv * w[lane];
    x1 *= inv * w[lane + 32];

    const float ang = (float)pos[s] * __expf(-(float)lane * (1.f / 32.f) * 9.2103403719761836f);
    float sn, c;
    sincosf(ang, &sn, &c);
    p[lane]      = f2tf32f((x0 * c - x1 * sn) * scale);
    p[lane + 32] = f2tf32f((x1 * c + x0 * sn) * scale);
}

// ---------------- causal flash attention (R13 form) ---------------------------
#define KPAD 68
#define VPAD 72
#define KTILE (64 * KPAD)
#define VTILE (64 * VPAD)
#define AT_SMEM_FLOATS (2 * KTILE + 2 * VTILE)
#define AT_SMEM_BYTES  (AT_SMEM_FLOATS * 4)    /* 71680 B */
#define L2E 1.4426950408889634f

__global__ __launch_bounds__(256, 2)
void attn_mma(const float* __restrict__ qb, const float* __restrict__ kb,
              const float* __restrict__ vb, float* __restrict__ ob)
{
    extern __shared__ float sm[];
    // layout: [Ks0, Ks1, Vs0, Vs1]

    const int tid = threadIdx.x;
    const int wid = tid >> 5;
    const int lane = tid & 31;
    const int g = lane >> 2;
    const int tg = lane & 3;
    const int nqt = SEQ / 128;
    const int qt = nqt - 1 - ((int)blockIdx.x >> 5);
    const int h = (int)blockIdx.x & 31;
    const int kvh = h >> 2;
    const int dlim = 2 * wid + 2;

    const int lr = tid >> 2;
    const int lc4 = (tid & 3) * 16;
    const uint32_t sbase = smem_u32(sm);
    const uint32_t sKrow = sbase + (uint32_t)(lr * KPAD + lc4) * 4u;
    const uint32_t sVrow = sbase + (uint32_t)(2 * KTILE + lr * VPAD + lc4) * 4u;
    const float* kbase = kb + (size_t)kvh * HD + lc4;
    const float* vbase = vb + (size_t)kvh * HD + lc4;

    // ---- Q fragments (pre-rounded, pre-scaled in gmem) ----
    uint32_t aq[8][4];
    {
        const float* qp = qb + (size_t)(qt * 128 + wid * 16) * QKVW + h * HD;
#pragma unroll
        for (int ks = 0; ks < 8; ks++) {
            const int c0 = ks * 8 + tg;
            aq[ks][0] = __float_as_uint(qp[(size_t)g * QKVW + c0]);
            aq[ks][1] = __float_as_uint(qp[(size_t)(g + 8) * QKVW + c0]);
            aq[ks][2] = __float_as_uint(qp[(size_t)g * QKVW + c0 + 4]);
            aq[ks][3] = __float_as_uint(qp[(size_t)(g + 8) * QKVW + c0 + 4]);
        }
    }

    float o[8][4];
#pragma unroll
    for (int nt = 0; nt < 8; nt++)
#pragma unroll
        for (int i = 0; i < 4; i++) o[nt][i] = 0.f;
    float m0 = -1e30f, m1 = -1e30f, l0 = 0.f, l1 = 0.f;

    const int r0g = qt * 128 + wid * 16 + g;
    const int r1g = r0g + 8;
    const int nkt = 2 * qt + 2;

    // ---- prefetch tile 0 ----
    {
        const float* kp = kbase + (size_t)lr * QKVW;
        const float* vp = vbase + (size_t)lr * QKVW;
#pragma unroll
        for (int j = 0; j < 4; j++) {
            CP_ASYNC16(sKrow + j * 16u, kp + j * 4);
            CP_ASYNC16(sVrow + j * 16u, vp + j * 4);
        }
        CP_COMMIT();
    }

    for (int kt = 0; kt < nkt; ++kt) {
        if (kt + 1 < nkt) {
            const uint32_t kb_off = (uint32_t)(((kt + 1) & 1) * KTILE) * 4u;
            const uint32_t vb_off = (uint32_t)(((kt + 1) & 1) * VTILE) * 4u;
            const float* kp = kbase + (size_t)((kt + 1) * 64 + lr) * QKVW;
            const float* vp = vbase + (size_t)((kt + 1) * 64 + lr) * QKVW;
#pragma unroll
            for (int j = 0; j < 4; j++) {
                CP_ASYNC16(sKrow + kb_off + j * 16u, kp + j * 4);
                CP_ASYNC16(sVrow + vb_off + j * 16u, vp + j * 4);
            }
            CP_COMMIT();
            CP_WAIT(1);
        } else {
            CP_WAIT(0);
        }
        __syncthreads();

        const float* Ks = sm + (kt & 1) * KTILE;
        const float* Vs = sm + 2 * KTILE + (kt & 1) * VTILE;

        const bool diag = (kt == 2 * qt);
        const bool active = !(kt == 2 * qt + 1 && wid < 4);
        if (active) {
            // ---- S = Q @ K^T ----
            float s[8][4];
#pragma unroll
            for (int nt = 0; nt < 8; nt++)
#pragma unroll
                for (int i = 0; i < 4; i++) s[nt][i] = 0.f;

#pragma unroll
            for (int ks = 0; ks < 8; ks++) {
                const int kk = ks * 8 + tg;
#pragma unroll
                for (int nt = 0; nt < 8; nt++) {
                    if (diag && nt >= dlim) continue;
                    const uint32_t b0 = __float_as_uint(Ks[(nt * 8 + g) * KPAD + kk]);
                    const uint32_t b1 = __float_as_uint(Ks[(nt * 8 + g) * KPAD + kk + 4]);
                    mma_tf32_16x8x8(s[nt][0], s[nt][1], s[nt][2], s[nt][3],
                                    aq[ks][0], aq[ks][1], aq[ks][2], aq[ks][3],
                                    b0, b1);
                }
            }

            // ---- causal mask ----
            if (kt >= 2 * qt) {
#pragma unroll
                for (int nt = 0; nt < 8; nt++) {
                    const int j0 = kt * 64 + nt * 8 + 2 * tg;
                    if (j0 > r0g)     s[nt][0] = -1e30f;
                    if (j0 + 1 > r0g) s[nt][1] = -1e30f;
                    if (j0 > r1g)     s[nt][2] = -1e30f;
                    if (j0 + 1 > r1g) s[nt][3] = -1e30f;
                }
            }

            // ---- online softmax ----
            float mx0 = -1e30f, mx1 = -1e30f;
#pragma unroll
            for (int nt = 0; nt < 8; nt++) {
                mx0 = fmaxf(mx0, fmaxf(s[nt][0], s[nt][1]));
                mx1 = fmaxf(mx1, fmaxf(s[nt][2], s[nt][3]));
            }
            mx0 = fmaxf(mx0, __shfl_xor_sync(0xffffffffu, mx0, 1));
            mx0 = fmaxf(mx0, __shfl_xor_sync(0xffffffffu, mx0, 2));
            mx1 = fmaxf(mx1, __shfl_xor_sync(0xffffffffu, mx1, 1));
            mx1 = fmaxf(mx1, __shfl_xor_sync(0xffffffffu, mx1, 2));

            const float mn0 = fmaxf(m0, mx0);
            const float mn1 = fmaxf(m1, mx1);
            const float al0 = ex2((m0 - mn0) * L2E);
            const float al1 = ex2((m1 - mn1) * L2E);
            float sum0 = 0.f, sum1 = 0.f;
#pragma unroll
            for (int nt = 0; nt < 8; nt++) {
                s[nt][0] = ex2((s[nt][0] - mn0) * L2E);
                s[nt][1] = ex2((s[nt][1] - mn0) * L2E);
                s[nt][2] = ex2((s[nt][2] - mn1) * L2E);
                s[nt][3] = ex2((s[nt][3] - mn1) * L2E);
                sum0 += s[nt][0] + s[nt][1];
                sum1 += s[nt][2] + s[nt][3];
            }
            sum0 += __shfl_xor_sync(0xffffffffu, sum0, 1);
            sum0 += __shfl_xor_sync(0xffffffffu, sum0, 2);
            sum1 += __shfl_xor_sync(0xffffffffu, sum1, 1);
            sum1 += __shfl_xor_sync(0xffffffffu, sum1, 2);
            m0 = mn0; m1 = mn1;
            l0 = l0 * al0 + sum0;
            l1 = l1 * al1 + sum1;
#pragma unroll
            for (int nt = 0; nt < 8; nt++) {
                o[nt][0] *= al0; o[nt][1] *= al0;
                o[nt][2] *= al1; o[nt][3] *= al1;
            }

            // ---- O += P @ V (A-frags via quad shuffles; conflict-free V) ----
            const int qbase = lane & ~3;
            const int s1 = qbase + (tg >> 1);
            const int s2 = s1 + 2;
            const bool odd = (tg & 1);
#pragma unroll
            for (int ks = 0; ks < 8; ks++) {
                if (diag && ks >= dlim) continue;
                const float v0 = __shfl_sync(0xffffffffu, s[ks][0], s1);
                const float v1 = __shfl_sync(0xffffffffu, s[ks][1], s1);
                const float v2 = __shfl_sync(0xffffffffu, s[ks][2], s1);
                const float v3 = __shfl_sync(0xffffffffu, s[ks][3], s1);
                const float w0 = __shfl_sync(0xffffffffu, s[ks][0], s2);
                const float w1 = __shfl_sync(0xffffffffu, s[ks][1], s2);
                const float w2 = __shfl_sync(0xffffffffu, s[ks][2], s2);
                const float w3 = __shfl_sync(0xffffffffu, s[ks][3], s2);
                const uint32_t a0 = f2tf32(odd ? v1 : v0);
                const uint32_t a1 = f2tf32(odd ? v3 : v2);
                const uint32_t a2 = f2tf32(odd ? w1 : w0);
                const uint32_t a3 = f2tf32(odd ? w3 : w2);
                const int kk = ks * 8 + tg;
#pragma unroll
                for (int nt = 0; nt < 8; nt++) {
                    const uint32_t b0 = __float_as_uint(Vs[kk * VPAD + nt * 8 + g]);
                    const uint32_t b1 = __float_as_uint(Vs[(kk + 4) * VPAD + nt * 8 + g]);
                    mma_tf32_16x8x8(o[nt][0], o[nt][1], o[nt][2], o[nt][3],
                                    a0, a1, a2, a3, b0, b1);
                }
            }
        }
        __syncthreads();
    }

    // ---- epilogue ----
    const float il0 = 1.f / l0;
    const float il1 = 1.f / l1;
#pragma unroll
    for (int nt = 0; nt < 8; nt++) {
        const int col = h * HD + nt * 8 + 2 * tg;
        *(float2*)(ob + (size_t)r0g * HID + col) =
            make_float2(f2tf32f(o[nt][0] * il0), f2tf32f(o[nt][1] * il0));
        *(float2*)(ob + (size_t)r1g * HID + col) =
            make_float2(f2tf32f(o[nt][2] * il1), f2tf32f(o[nt][3] * il1));
    }
}

// ---------------- launch ------------------------------------------------------
extern "C" void kernel_launch(void* const* d_in, const int* in_sizes, int n_in,
                              void* d_out, int out_size)
{
    const float* hs  = (const float*)d_in[0];
    const int*   pos = (const int*)  d_in[1];
    const float* wq  = (const float*)d_in[2];
    const float* wk  = (const float*)d_in[3];
    const float* wv  = (const float*)d_in[4];
    const float* wo  = (const float*)d_in[5];
    const float* qw  = (const float*)d_in[6];
    const float* kw  = (const float*)d_in[7];
    float* out = (float*)d_out;

    float *pqkv, *pa, *phs, *pwqkvT, *pwoT;
    cudaGetSymbolAddress((void**)&pqkv, g_qkv);
    cudaGetSymbolAddress((void**)&pa, g_att);
    cudaGetSymbolAddress((void**)&phs, g_hs32);
    cudaGetSymbolAddress((void**)&pwqkvT, g_wqkvT);
    cudaGetSymbolAddress((void**)&pwoT, g_woT);

    cudaFuncSetAttribute(gemm_mma, cudaFuncAttributeMaxDynamicSharedMemorySize,
                         G_SMEM_BYTES);
    cudaFuncSetAttribute(attn_mma, cudaFuncAttributeMaxDynamicSharedMemorySize,
                         AT_SMEM_BYTES);

    prep_copy<<<4096, 256>>>(hs, phs);                       // launch 0
    prep_wqkv<<<6144, 256>>>(wq, wk, wv, pwqkvT);            // launch 1
    prep_wo<<<4096, 256>>>(wo, pwoT);                        // launch 2

    // launch 3 (ncu-captured): fused QKV projection
    gemm_mma<<<dim3(QKVW / 128, SEQ / 128), 256, G_SMEM_BYTES>>>(phs, pwqkvT, pqkv, SEQ, QKVW, HID, 1);

    norm_rope_all<<<10240, 256>>>(pqkv, qw, kw, pos);        // launch 4

    float* pk = pqkv + HID;
    float* pv = pqkv + HID + KVW;
    attn_mma<<<512, 256, AT_SMEM_BYTES>>>(pqkv, pk, pv, pa); // launch 5

    gemm_mma<<<dim3(HID / 128, SEQ / 128), 256, G_SMEM_BYTES>>>(pa, pwoT, out, SEQ, HID, HID, 0);
}

// round 16
// speedup vs baseline: 1.6554x; 1.5701x over previous
#include <cuda_runtime.h>
#include <cuda_fp16.h>
#include <math.h>
#include <stdint.h>

#define SEQ 2048
#define HID 2048
#define NH 32
#define NKV 8
#define HD 64
#define KVW (NKV*HD)       /* 512 */
#define QKVW (HID + 2*KVW) /* 3072 */

// ---------------- scratch ------------------------------------------------------
__device__ float  g_qkv[SEQ * QKVW];        // fp32 (tf32-rounded) q|k|v for attention
__device__ __half g_hs16[SEQ * HID];        // fp16 hidden states
__device__ __half g_wqkv16[QKVW * HID];     // fp16 transposed qkv weights
__device__ __half g_wo16[HID * HID];        // fp16 transposed wo
__device__ __half g_att16[SEQ * HID];       // fp16 attention output (O-proj A operand)

// ================= helpers =================
__device__ __forceinline__ uint32_t smem_u32(const void* p) {
    uint32_t a;
    asm("{ .reg .u64 t; cvta.to.shared.u64 t, %1; cvt.u32.u64 %0, t; }" : "=r"(a) : "l"(p));
    return a;
}
__device__ __forceinline__ uint32_t f2tf32(float f) {
    uint32_t r;
    asm("cvt.rna.tf32.f32 %0, %1;" : "=r"(r) : "f"(f));
    return r;
}
__device__ __forceinline__ float f2tf32f(float f) {
    return __uint_as_float(f2tf32(f));
}
__device__ __forceinline__ float ex2(float x) {
    float r;
    asm("ex2.approx.ftz.f32 %0, %1;" : "=f"(r) : "f"(x));
    return r;
}
#define CP_ASYNC16(dst, src) \
    asm volatile("cp.async.cg.shared.global [%0], [%1], 16;" :: "r"(dst), "l"(src))
#define CP_COMMIT() asm volatile("cp.async.commit_group;" ::: "memory")
#define CP_WAIT(n)  asm volatile("cp.async.wait_group %0;" :: "n"(n) : "memory")

__device__ __forceinline__ void mma_tf32_16x8x8(float& c0, float& c1, float& c2, float& c3,
                                                uint32_t a0, uint32_t a1, uint32_t a2, uint32_t a3,
                                                uint32_t b0, uint32_t b1) {
    asm volatile(
        "mma.sync.aligned.m16n8k8.row.col.f32.tf32.tf32.f32 "
        "{%0,%1,%2,%3}, {%4,%5,%6,%7}, {%8,%9}, {%0,%1,%2,%3};"
        : "+f"(c0), "+f"(c1), "+f"(c2), "+f"(c3)
        : "r"(a0), "r"(a1), "r"(a2), "r"(a3), "r"(b0), "r"(b1));
}
__device__ __forceinline__ void mma_f16_16x8x16(float& c0, float& c1, float& c2, float& c3,
                                                uint32_t a0, uint32_t a1, uint32_t a2, uint32_t a3,
                                                uint32_t b0, uint32_t b1) {
    asm volatile(
        "mma.sync.aligned.m16n8k16.row.col.f32.f16.f16.f32 "
        "{%0,%1,%2,%3}, {%4,%5,%6,%7}, {%8,%9}, {%0,%1,%2,%3};"
        : "+f"(c0), "+f"(c1), "+f"(c2), "+f"(c3)
        : "r"(a0), "r"(a1), "r"(a2), "r"(a3), "r"(b0), "r"(b1));
}

// ---------------- prep 0: hs -> fp16 ------------------------------------------
__global__ __launch_bounds__(256)
void prep_copy(const float* __restrict__ hs, __half* __restrict__ hs16)
{
    const int i = (blockIdx.x * 256 + threadIdx.x) * 4;
    float4 v = *(const float4*)(hs + i);
    *(__half2*)(hs16 + i)     = __floats2half2_rn(v.x, v.y);
    *(__half2*)(hs16 + i + 2) = __floats2half2_rn(v.z, v.w);
}

// ---------------- prep 1: wq/wk/wv transpose -> fp16 --------------------------
__global__ __launch_bounds__(256)
void prep_wqkv(const float* __restrict__ wq, const float* __restrict__ wk,
               const float* __restrict__ wv, __half* __restrict__ wqkvT)
{
    __shared__ float t[32][33];
    const int bx = blockIdx.x;
    const int tx = threadIdx.x & 31;
    const int ty = threadIdx.x >> 5;
    const float* in;
    __half* out;
    int N, lb;
    if (bx < 4096)       { in = wq; out = wqkvT;                          N = HID; lb = bx; }
    else if (bx < 5120)  { in = wk; out = wqkvT + (size_t)HID * HID;      N = KVW; lb = bx - 4096; }
    else                 { in = wv; out = wqkvT + (size_t)(HID+KVW)*HID;  N = KVW; lb = bx - 5120; }
    const int gw = N / 32;
    const int bxx = (lb % gw) * 32;
    const int byy = (lb / gw) * 32;
#pragma unroll
    for (int i = 0; i < 32; i += 8)
        t[ty + i][tx] = in[(size_t)(byy + ty + i) * N + bxx + tx];
    __syncthreads();
#pragma unroll
    for (int i = 0; i < 32; i += 8)
        out[(size_t)(bxx + ty + i) * HID + byy + tx] = __float2half_rn(t[tx][ty + i]);
}

// ---------------- prep 2: wo transpose -> fp16 --------------------------------
__global__ __launch_bounds__(256)
void prep_wo(const float* __restrict__ wo, __half* __restrict__ woT)
{
    __shared__ float t[32][33];
    const int bxx = ((int)blockIdx.x % 64) * 32;
    const int byy = ((int)blockIdx.x / 64) * 32;
    const int tx = threadIdx.x & 31;
    const int ty = threadIdx.x >> 5;
#pragma unroll
    for (int i = 0; i < 32; i += 8)
        t[ty + i][tx] = wo[(size_t)(byy + ty + i) * HID + bxx + tx];
    __syncthreads();
#pragma unroll
    for (int i = 0; i < 32; i += 8)
        woT[(size_t)(bxx + ty + i) * HID + byy + tx] = __float2half_rn(t[tx][ty + i]);
}

// ---------------- fp16 mma.sync GEMM: 3-stage pipeline, 1 barrier/chunk -------
// BK = 32 halves (2 k16 steps). smem row stride = 20 uints (16 data + 4 pad):
// fragment LDS banks 20g+tg all distinct -> conflict-free.
#define GSTR 20                       /* uints per row */
#define GBUFU (128 * GSTR)            /* uints per operand per stage */
#define G_SMEM_BYTES (6 * GBUFU * 4)  /* 3 stages x (A+B) = 61440 B */

__global__ __launch_bounds__(256, 2)
void gemm_f16(const __half* __restrict__ A, const __half* __restrict__ BT,
              float* __restrict__ C, int M, int N, int K, int roundOut)
{
    extern __shared__ float sm[];
    uint32_t* smu = (uint32_t*)sm;

    const int tid  = threadIdx.x;
    const int wid  = tid >> 5;
    const int lane = tid & 31;
    const int g    = lane >> 2;
    const int tg   = lane & 3;
    const int wm   = (wid & 3) * 32;
    const int wn   = (wid >> 2) * 64;
    const int m0 = blockIdx.y * 128;
    const int n0 = blockIdx.x * 128;

    // loader: 2 threads per row, 16 halves (32B) each = 2 cp.async
    const int lrow  = tid >> 1;
    const int lch   = (tid & 1) * 16;          // half offset within 32-half chunk
    const __half* gA = A  + (size_t)(m0 + lrow) * K + lch;
    const __half* gB = BT + (size_t)(n0 + lrow) * K + lch;
    const uint32_t sbase = smem_u32(sm);
    const uint32_t sArow = sbase + (uint32_t)(lrow * GSTR) * 4u + (uint32_t)(tid & 1) * 32u;
    const uint32_t sBrow = sArow + 3u * GBUFU * 4u;

    float acc[2][8][4];
#pragma unroll
    for (int mt = 0; mt < 2; mt++)
#pragma unroll
        for (int nt = 0; nt < 8; nt++)
#pragma unroll
            for (int i = 0; i < 4; i++) acc[mt][nt][i] = 0.f;

    const int nch = K >> 5;   // chunks of 32 halves

    // prologue: prefetch chunks 0,1 into stages 0,1
#pragma unroll
    for (int p = 0; p < 2; ++p) {
        const uint32_t soff = (uint32_t)(p * GBUFU) * 4u;
        const __half* pa = gA + p * 32;
        const __half* pb = gB + p * 32;
#pragma unroll
        for (int j = 0; j < 2; j++) {
            CP_ASYNC16(sArow + soff + j * 16u, pa + j * 8);
            CP_ASYNC16(sBrow + soff + j * 16u, pb + j * 8);
        }
        CP_COMMIT();
    }

    for (int c = 0; c < nch; ++c) {
        if (c + 1 < nch) CP_WAIT(1); else CP_WAIT(0);
        __syncthreads();   // publish chunk c; stage (c+2)%3 reusable

        if (c + 2 < nch) {
            const uint32_t soff = (uint32_t)(((c + 2) % 3) * GBUFU) * 4u;
            const __half* pa = gA + (c + 2) * 32;
            const __half* pb = gB + (c + 2) * 32;
#pragma unroll
            for (int j = 0; j < 2; j++) {
                CP_ASYNC16(sArow + soff + j * 16u, pa + j * 8);
                CP_ASYNC16(sBrow + soff + j * 16u, pb + j * 8);
            }
            CP_COMMIT();
        }

        const uint32_t* tA = smu + (c % 3) * GBUFU;
        const uint32_t* tB = smu + 3 * GBUFU + (c % 3) * GBUFU;

#pragma unroll
        for (int ks = 0; ks < 2; ++ks) {
            const int kb = ks * 8;     // uint offset of this k16 step
            uint32_t af[2][4];
#pragma unroll
            for (int mt = 0; mt < 2; mt++) {
                const int r = wm + mt * 16 + g;
                af[mt][0] = tA[r * GSTR + kb + tg];
                af[mt][1] = tA[(r + 8) * GSTR + kb + tg];
                af[mt][2] = tA[r * GSTR + kb + tg + 4];
                af[mt][3] = tA[(r + 8) * GSTR + kb + tg + 4];
            }
            uint32_t bf[8][2];
#pragma unroll
            for (int nt = 0; nt < 8; nt++) {
                const int r = wn + nt * 8 + g;
                bf[nt][0] = tB[r * GSTR + kb + tg];
                bf[nt][1] = tB[r * GSTR + kb + tg + 4];
            }
#pragma unroll
            for (int mt = 0; mt < 2; mt++)
#pragma unroll
                for (int nt = 0; nt < 8; nt++)
                    mma_f16_16x8x16(acc[mt][nt][0], acc[mt][nt][1],
                                    acc[mt][nt][2], acc[mt][nt][3],
                                    af[mt][0], af[mt][1], af[mt][2], af[mt][3],
                                    bf[nt][0], bf[nt][1]);
        }
    }

#pragma unroll
    for (int mt = 0; mt < 2; mt++) {
        const int r0 = m0 + wm + mt * 16 + g;
#pragma unroll
        for (int nt = 0; nt < 8; nt++) {
            const int col = n0 + wn + nt * 8 + 2 * tg;
            float2 v0 = make_float2(acc[mt][nt][0], acc[mt][nt][1]);
            float2 v1 = make_float2(acc[mt][nt][2], acc[mt][nt][3]);
            if (roundOut) {
                v0.x = f2tf32f(v0.x); v0.y = f2tf32f(v0.y);
                v1.x = f2tf32f(v1.x); v1.y = f2tf32f(v1.y);
            }
            *(float2*)(C + (size_t)r0 * N + col) = v0;
            *(float2*)(C + (size_t)(r0 + 8) * N + col) = v1;
        }
    }
}

// ---------------- fused RMSNorm + RoPE (q + k in one launch) ------------------
__global__ __launch_bounds__(256)
void norm_rope_all(float* __restrict__ qkv, const float* __restrict__ qw,
                   const float* __restrict__ kw, const int* __restrict__ pos)
{
    const int bx = blockIdx.x;
    float* x; const float* w; int nheads; float scale; int lb;
    if (bx < 8192) { x = qkv;       w = qw; nheads = NH;  scale = 0.125f; lb = bx; }
    else           { x = qkv + HID; w = kw; nheads = NKV; scale = 1.0f;   lb = bx - 8192; }

    const int gw = (lb * 256 + (int)threadIdx.x) >> 5;
    const int lane = threadIdx.x & 31;
    const int s = gw / nheads;
    const int hh = gw - s * nheads;

    float* p = x + (size_t)s * QKVW + hh * HD;
    float x0 = p[lane];
    float x1 = p[lane + 32];

    float ss = x0 * x0 + x1 * x1;
#pragma unroll
    for (int o = 16; o; o >>= 1) ss += __shfl_xor_sync(0xffffffffu, ss, o);
    const float inv = rsqrtf(ss * (1.f / 64.f) + 1e-6f);
    x0 *= inv * w[lane];
    x1 *= inv * w[lane + 32];

    const float ang = (float)pos[s] * __expf(-(float)lane * (1.f / 32.f) * 9.2103403719761836f);
    float sn, c;
    sincosf(ang, &sn, &c);
    p[lane]      = f2tf32f((x0 * c - x1 * sn) * scale);
    p[lane + 32] = f2tf32f((x1 * c + x0 * sn) * scale);
}

// ---------------- causal flash attention (R13/R15 form, fp16 epilogue) --------
#define KPAD 68
#define VPAD 72
#define KTILE (64 * KPAD)
#define VTILE (64 * VPAD)
#define AT_SMEM_FLOATS (2 * KTILE + 2 * VTILE)
#define AT_SMEM_BYTES  (AT_SMEM_FLOATS * 4)    /* 71680 B */
#define L2E 1.4426950408889634f

__global__ __launch_bounds__(256, 2)
void attn_mma(const float* __restrict__ qb, const float* __restrict__ kb,
              const float* __restrict__ vb, __half* __restrict__ ob)
{
    extern __shared__ float sm[];
    // layout: [Ks0, Ks1, Vs0, Vs1]

    const int tid = threadIdx.x;
    const int wid = tid >> 5;
    const int lane = tid & 31;
    const int g = lane >> 2;
    const int tg = lane & 3;
    const int nqt = SEQ / 128;
    const int qt = nqt - 1 - ((int)blockIdx.x >> 5);
    const int h = (int)blockIdx.x & 31;
    const int kvh = h >> 2;
    const int dlim = 2 * wid + 2;

    const int lr = tid >> 2;
    const int lc4 = (tid & 3) * 16;
    const uint32_t sbase = smem_u32(sm);
    const uint32_t sKrow = sbase + (uint32_t)(lr * KPAD + lc4) * 4u;
    const uint32_t sVrow = sbase + (uint32_t)(2 * KTILE + lr * VPAD + lc4) * 4u;
    const float* kbase = kb + (size_t)kvh * HD + lc4;
    const float* vbase = vb + (size_t)kvh * HD + lc4;

    // ---- Q fragments (pre-rounded, pre-scaled in gmem) ----
    uint32_t aq[8][4];
    {
        const float* qp = qb + (size_t)(qt * 128 + wid * 16) * QKVW + h * HD;
#pragma unroll
        for (int ks = 0; ks < 8; ks++) {
            const int c0 = ks * 8 + tg;
            aq[ks][0] = __float_as_uint(qp[(size_t)g * QKVW + c0]);
            aq[ks][1] = __float_as_uint(qp[(size_t)(g + 8) * QKVW + c0]);
            aq[ks][2] = __float_as_uint(qp[(size_t)g * QKVW + c0 + 4]);
            aq[ks][3] = __float_as_uint(qp[(size_t)(g + 8) * QKVW + c0 + 4]);
        }
    }

    float o[8][4];
#pragma unroll
    for (int nt = 0; nt < 8; nt++)
#pragma unroll
        for (int i = 0; i < 4; i++) o[nt][i] = 0.f;
    float m0 = -1e30f, m1 = -1e30f, l0 = 0.f, l1 = 0.f;

    const int r0g = qt * 128 + wid * 16 + g;
    const int r1g = r0g + 8;
    const int nkt = 2 * qt + 2;

    // ---- prefetch tile 0 ----
    {
        const float* kp = kbase + (size_t)lr * QKVW;
        const float* vp = vbase + (size_t)lr * QKVW;
#pragma unroll
        for (int j = 0; j < 4; j++) {
            CP_ASYNC16(sKrow + j * 16u, kp + j * 4);
            CP_ASYNC16(sVrow + j * 16u, vp + j * 4);
        }
        CP_COMMIT();
    }

    for (int kt = 0; kt < nkt; ++kt) {
        if (kt + 1 < nkt) {
            const uint32_t kb_off = (uint32_t)(((kt + 1) & 1) * KTILE) * 4u;
            const uint32_t vb_off = (uint32_t)(((kt + 1) & 1) * VTILE) * 4u;
            const float* kp = kbase + (size_t)((kt + 1) * 64 + lr) * QKVW;
            const float* vp = vbase + (size_t)((kt + 1) * 64 + lr) * QKVW;
#pragma unroll
            for (int j = 0; j < 4; j++) {
                CP_ASYNC16(sKrow + kb_off + j * 16u, kp + j * 4);
                CP_ASYNC16(sVrow + vb_off + j * 16u, vp + j * 4);
            }
            CP_COMMIT();
            CP_WAIT(1);
        } else {
            CP_WAIT(0);
        }
        __syncthreads();

        const float* Ks = sm + (kt & 1) * KTILE;
        const float* Vs = sm + 2 * KTILE + (kt & 1) * VTILE;

        const bool diag = (kt == 2 * qt);
        const bool active = !(kt == 2 * qt + 1 && wid < 4);
        if (active) {
            // ---- S = Q @ K^T ----
            float s[8][4];
#pragma unroll
            for (int nt = 0; nt < 8; nt++)
#pragma unroll
                for (int i = 0; i < 4; i++) s[nt][i] = 0.f;

#pragma unroll
            for (int ks = 0; ks < 8; ks++) {
                const int kk = ks * 8 + tg;
#pragma unroll
                for (int nt = 0; nt < 8; nt++) {
                    if (diag && nt >= dlim) continue;
                    const uint32_t b0 = __float_as_uint(Ks[(nt * 8 + g) * KPAD + kk]);
                    const uint32_t b1 = __float_as_uint(Ks[(nt * 8 + g) * KPAD + kk + 4]);
                    mma_tf32_16x8x8(s[nt][0], s[nt][1], s[nt][2], s[nt][3],
                                    aq[ks][0], aq[ks][1], aq[ks][2], aq[ks][3],
                                    b0, b1);
                }
            }

            // ---- causal mask ----
            if (kt >= 2 * qt) {
#pragma unroll
                for (int nt = 0; nt < 8; nt++) {
                    const int j0 = kt * 64 + nt * 8 + 2 * tg;
                    if (j0 > r0g)     s[nt][0] = -1e30f;
                    if (j0 + 1 > r0g) s[nt][1] = -1e30f;
                    if (j0 > r1g)     s[nt][2] = -1e30f;
                    if (j0 + 1 > r1g) s[nt][3] = -1e30f;
                }
            }

            // ---- online softmax ----
            float mx0 = -1e30f, mx1 = -1e30f;
#pragma unroll
            for (int nt = 0; nt < 8; nt++) {
                mx0 = fmaxf(mx0, fmaxf(s[nt][0], s[nt][1]));
                mx1 = fmaxf(mx1, fmaxf(s[nt][2], s[nt][3]));
            }
            mx0 = fmaxf(mx0, __shfl_xor_sync(0xffffffffu, mx0, 1));
            mx0 = fmaxf(mx0, __shfl_xor_sync(0xffffffffu, mx0, 2));
            mx1 = fmaxf(mx1, __shfl_xor_sync(0xffffffffu, mx1, 1));
            mx1 = fmaxf(mx1, __shfl_xor_sync(0xffffffffu, mx1, 2));

            const float mn0 = fmaxf(m0, mx0);
            const float mn1 = fmaxf(m1, mx1);
            const float al0 = ex2((m0 - mn0) * L2E);
            const float al1 = ex2((m1 - mn1) * L2E);
            float sum0 = 0.f, sum1 = 0.f;
#pragma unroll
            for (int nt = 0; nt < 8; nt++) {
                s[nt][0] = ex2((s[nt][0] - mn0) * L2E);
                s[nt][1] = ex2((s[nt][1] - mn0) * L2E);
                s[nt][2] = ex2((s[nt][2] - mn1) * L2E);
                s[nt][3] = ex2((s[nt][3] - mn1) * L2E);
                sum0 += s[nt][0] + s[nt][1];
                sum1 += s[nt][2] + s[nt][3];
            }
            sum0 += __shfl_xor_sync(0xffffffffu, sum0, 1);
            sum0 += __shfl_xor_sync(0xffffffffu, sum0, 2);
            sum1 += __shfl_xor_sync(0xffffffffu, sum1, 1);
            sum1 += __shfl_xor_sync(0xffffffffu, sum1, 2);
            m0 = mn0; m1 = mn1;
            l0 = l0 * al0 + sum0;
            l1 = l1 * al1 + sum1;
#pragma unroll
            for (int nt = 0; nt < 8; nt++) {
                o[nt][0] *= al0; o[nt][1] *= al0;
                o[nt][2] *= al1; o[nt][3] *= al1;
            }

            // ---- O += P @ V ----
            const int qbase = lane & ~3;
            const int s1 = qbase + (tg >> 1);
            const int s2 = s1 + 2;
            const bool odd = (tg & 1);
#pragma unroll
            for (int ks = 0; ks < 8; ks++) {
                if (diag && ks >= dlim) continue;
                const float v0 = __shfl_sync(0xffffffffu, s[ks][0], s1);
                const float v1 = __shfl_sync(0xffffffffu, s[ks][1], s1);
                const float v2 = __shfl_sync(0xffffffffu, s[ks][2], s1);
                const float v3 = __shfl_sync(0xffffffffu, s[ks][3], s1);
                const float w0 = __shfl_sync(0xffffffffu, s[ks][0], s2);
                const float w1 = __shfl_sync(0xffffffffu, s[ks][1], s2);
                const float w2 = __shfl_sync(0xffffffffu, s[ks][2], s2);
                const float w3 = __shfl_sync(0xffffffffu, s[ks][3], s2);
                const uint32_t a0 = f2tf32(odd ? v1 : v0);
                const uint32_t a1 = f2tf32(odd ? v3 : v2);
                const uint32_t a2 = f2tf32(odd ? w1 : w0);
                const uint32_t a3 = f2tf32(odd ? w3 : w2);
                const int kk = ks * 8 + tg;
#pragma unroll
                for (int nt = 0; nt < 8; nt++) {
                    const uint32_t b0 = __float_as_uint(Vs[kk * VPAD + nt * 8 + g]);
                    const uint32_t b1 = __float_as_uint(Vs[(kk + 4) * VPAD + nt * 8 + g]);
                    mma_tf32_16x8x8(o[nt][0], o[nt][1], o[nt][2], o[nt][3],
                                    a0, a1, a2, a3, b0, b1);
                }
            }
        }
        __syncthreads();
    }

    // ---- epilogue: write fp16 (fp16 round = rounding for O-proj A) ----
    const float il0 = 1.f / l0;
    const float il1 = 1.f / l1;
#pragma unroll
    for (int nt = 0; nt < 8; nt++) {
        const int col = h * HD + nt * 8 + 2 * tg;
        *(__half2*)(ob + (size_t)r0g * HID + col) =
            __floats2half2_rn(o[nt][0] * il0, o[nt][1] * il0);
        *(__half2*)(ob + (size_t)r1g * HID + col) =
            __floats2half2_rn(o[nt][2] * il1, o[nt][3] * il1);
    }
}

// ---------------- launch ------------------------------------------------------
extern "C" void kernel_launch(void* const* d_in, const int* in_sizes, int n_in,
                              void* d_out, int out_size)
{
    const float* hs  = (const float*)d_in[0];
    const int*   pos = (const int*)  d_in[1];
    const float* wq  = (const float*)d_in[2];
    const float* wk  = (const float*)d_in[3];
    const float* wv  = (const float*)d_in[4];
    const float* wo  = (const float*)d_in[5];
    const float* qw  = (const float*)d_in[6];
    const float* kw  = (const float*)d_in[7];
    float* out = (float*)d_out;

    float *pqkv;
    __half *phs16, *pwqkv16, *pwo16, *patt16;
    cudaGetSymbolAddress((void**)&pqkv, g_qkv);
    cudaGetSymbolAddress((void**)&phs16, g_hs16);
    cudaGetSymbolAddress((void**)&pwqkv16, g_wqkv16);
    cudaGetSymbolAddress((void**)&pwo16, g_wo16);
    cudaGetSymbolAddress((void**)&patt16, g_att16);

    cudaFuncSetAttribute(gemm_f16, cudaFuncAttributeMaxDynamicSharedMemorySize,
                         G_SMEM_BYTES);
    cudaFuncSetAttribute(attn_mma, cudaFuncAttributeMaxDynamicSharedMemorySize,
                         AT_SMEM_BYTES);

    prep_copy<<<4096, 256>>>(hs, phs16);                     // launch 0
    prep_wqkv<<<6144, 256>>>(wq, wk, wv, pwqkv16);           // launch 1
    prep_wo<<<4096, 256>>>(wo, pwo16);                       // launch 2

    // launch 3 (ncu-captured): fused QKV projection, fp16 inputs, tf32-rounded fp32 out
    gemm_f16<<<dim3(QKVW / 128, SEQ / 128), 256, G_SMEM_BYTES>>>(phs16, pwqkv16, pqkv, SEQ, QKVW, HID, 1);

    norm_rope_all<<<10240, 256>>>(pqkv, qw, kw, pos);        // launch 4

    float* pk = pqkv + HID;
    float* pv = pqkv + HID + KVW;
    attn_mma<<<512, 256, AT_SMEM_BYTES>>>(pqkv, pk, pv, patt16); // launch 5

    // launch 6: O-projection, fp16 inputs, fp32 output
    gemm_f16<<<dim3(HID / 128, SEQ / 128), 256, G_SMEM_BYTES>>>(patt16, pwo16, out, SEQ, HID, HID, 0);
}